// round 5
// baseline (speedup 1.0000x reference)
#include <cuda_runtime.h>
#include <math.h>

// Problem constants
#define BB 2
#define SS 2048
#define DD 1024
#define HH 16
#define DKK 64
#define MM (BB * SS)          // 4096
#define SCALE 0.125f          // 1/sqrt(64)

// Scratch (allocation-free rule: __device__ globals)
__device__ float g_Q[BB * HH * SS * DKK];   // [B,H,S,DK]
__device__ float g_K[BB * HH * SS * DKK];
__device__ float g_V[BB * HH * SS * DKK];
__device__ float g_O[BB * SS * DD];         // [B,S,D]

// ---------------------------------------------------------------------------
// SGEMM: C[M=4096, N=1024] = A[M,1024] @ W[1024,N] + bias
// 64x64 tile, BK=16, 256 threads, 4x4 microtile, float4 smem reads.
// HEAD_LAYOUT: write out[((b*H+h)*S+s)*DK+dk] instead of out[m*1024+n].
// ---------------------------------------------------------------------------
template <bool HEAD_LAYOUT>
__global__ __launch_bounds__(256) void sgemm_kernel(
    const float* __restrict__ A, const float* __restrict__ W,
    const float* __restrict__ bias, float* __restrict__ out)
{
    __shared__ float As[16 * 68];   // As[k][m] (transposed)
    __shared__ float Bs[16 * 68];   // Bs[k][n]

    const int tid = threadIdx.x;
    const int tx = tid & 15;
    const int ty = tid >> 4;
    const int m0 = blockIdx.y * 64;
    const int n0 = blockIdx.x * 64;

    const int aRow = tid >> 2;            // 0..63
    const int aCol = (tid & 3) << 2;      // 0,4,8,12
    const int bRow = tid >> 4;            // 0..15
    const int bCol = (tid & 15) << 2;     // 0..60

    float acc[4][4] = {};

    for (int k0 = 0; k0 < DD; k0 += 16) {
        float4 av = *(const float4*)(A + (size_t)(m0 + aRow) * DD + k0 + aCol);
        float4 bv = *(const float4*)(W + (size_t)(k0 + bRow) * DD + n0 + bCol);
        __syncthreads();
        As[(aCol + 0) * 68 + aRow] = av.x;
        As[(aCol + 1) * 68 + aRow] = av.y;
        As[(aCol + 2) * 68 + aRow] = av.z;
        As[(aCol + 3) * 68 + aRow] = av.w;
        *(float4*)(Bs + bRow * 68 + bCol) = bv;
        __syncthreads();
#pragma unroll
        for (int kk = 0; kk < 16; ++kk) {
            float4 a = *(const float4*)(As + kk * 68 + (ty << 2));
            float4 b = *(const float4*)(Bs + kk * 68 + (tx << 2));
            float ar[4] = {a.x, a.y, a.z, a.w};
            float br[4] = {b.x, b.y, b.z, b.w};
#pragma unroll
            for (int i = 0; i < 4; ++i)
#pragma unroll
                for (int j = 0; j < 4; ++j)
                    acc[i][j] += ar[i] * br[j];
        }
    }

#pragma unroll
    for (int i = 0; i < 4; ++i) {
        int m = m0 + (ty << 2) + i;
#pragma unroll
        for (int j = 0; j < 4; ++j) {
            int n = n0 + (tx << 2) + j;
            float v = acc[i][j] + bias[n];
            if (HEAD_LAYOUT) {
                int h = n >> 6, dk = n & 63;
                int b = m >> 11, s = m & 2047;
                out[(((size_t)(b * HH + h) * SS) + s) * DKK + dk] = v;
            } else {
                out[(size_t)m * DD + n] = v;
            }
        }
    }
}

// ---------------------------------------------------------------------------
// RoPE on g_Q and g_K in-place. One thread per (b,h,s,pair).
// Angle computed in double with range reduction -> bounded error vs fp32 ref.
// ---------------------------------------------------------------------------
__global__ __launch_bounds__(256) void rope_kernel(const int* __restrict__ pos)
{
    int idx = blockIdx.x * blockDim.x + threadIdx.x;
    if (idx >= BB * HH * SS * (DKK / 2)) return;
    int i = idx & 31;
    int s = (idx >> 5) & 2047;
    int h = (idx >> 16) & 15;
    int b = idx >> 20;

    int p = pos[b * SS + s];
    // inv_freq = 10000^(-i/32) = exp(-i * ln(10000)/32)
    double inv = exp(-(double)i * 0.28782313662425575);
    double ang = (double)p * inv;
    ang = fmod(ang, 6.283185307179586476925286766559);
    float c = cosf((float)ang);
    float sn = sinf((float)ang);

    size_t base = (((size_t)(b * HH + h) * SS) + s) * DKK + 2 * i;
    float q0 = g_Q[base], q1 = g_Q[base + 1];
    g_Q[base]     = q0 * c - q1 * sn;
    g_Q[base + 1] = q0 * sn + q1 * c;
    float k0 = g_K[base], k1 = g_K[base + 1];
    g_K[base]     = k0 * c - k1 * sn;
    g_K[base + 1] = k0 * sn + k1 * c;
}

// ---------------------------------------------------------------------------
// Flash attention (fp32, causal). One block = 64 query rows of one (b,h).
// 256 threads, 4x4 microtiles over the 64x64 score tile. Online softmax.
// Dynamic smem: Qs/Ks (transposed, [d][r]), Vs [c][j], Ps (transposed [c][r]),
// all pitch 68 floats (16B-aligned rows, odd bank stride).
// ---------------------------------------------------------------------------
__global__ __launch_bounds__(256) void flash_kernel()
{
    extern __shared__ float sm[];
    float* Qs = sm;               // Qs[d*68 + r]
    float* Ks = sm + 64 * 68;     // Ks[d*68 + c]
    float* Vs = sm + 2 * 64 * 68; // Vs[c*68 + j]
    float* Ps = sm + 3 * 64 * 68; // Ps[c*68 + r]

    const int qt = (int)gridDim.x - 1 - (int)blockIdx.x;  // heavy tiles first
    const int h = blockIdx.y;
    const int b = blockIdx.z;
    const int q0 = qt * 64;
    const int tid = threadIdx.x;
    const int tx = tid & 15;
    const int ty = tid >> 4;

    const float* Qg = g_Q + ((size_t)(b * HH + h) * SS) * DKK;
    const float* Kg = g_K + ((size_t)(b * HH + h) * SS) * DKK;
    const float* Vg = g_V + ((size_t)(b * HH + h) * SS) * DKK;

    // Load Q tile transposed
    for (int idx = tid; idx < 4096; idx += 256) {
        int r = idx >> 6, d = idx & 63;
        Qs[d * 68 + r] = Qg[(size_t)(q0 + r) * DKK + d];
    }

    float o[4][4] = {};
    float mrow[4] = {-1e30f, -1e30f, -1e30f, -1e30f};
    float lrow[4] = {};

    const int nTiles = qt + 1;
    for (int t = 0; t < nTiles; ++t) {
        const int j0 = t * 64;
        __syncthreads();
        for (int idx = tid; idx < 4096; idx += 256) {
            int r = idx >> 6, d = idx & 63;
            Ks[d * 68 + r] = Kg[(size_t)(j0 + r) * DKK + d];
            Vs[r * 68 + d] = Vg[(size_t)(j0 + r) * DKK + d];
        }
        __syncthreads();

        float s[4][4] = {};
#pragma unroll 8
        for (int d = 0; d < 64; ++d) {
            float4 a = *(const float4*)(Qs + d * 68 + (ty << 2));
            float4 bb = *(const float4*)(Ks + d * 68 + (tx << 2));
            float ar[4] = {a.x, a.y, a.z, a.w};
            float br[4] = {bb.x, bb.y, bb.z, bb.w};
#pragma unroll
            for (int i = 0; i < 4; ++i)
#pragma unroll
                for (int j = 0; j < 4; ++j)
                    s[i][j] += ar[i] * br[j];
        }

        const bool diag = (t == qt);
#pragma unroll
        for (int i = 0; i < 4; ++i)
#pragma unroll
            for (int j = 0; j < 4; ++j) {
                float v = s[i][j] * SCALE;
                if (diag && ((tx << 2) + j) > ((ty << 2) + i)) v = -1e30f;
                s[i][j] = v;
            }

        float mnew[4], alpha[4];
#pragma unroll
        for (int i = 0; i < 4; ++i) {
            float rm = fmaxf(fmaxf(s[i][0], s[i][1]), fmaxf(s[i][2], s[i][3]));
#pragma unroll
            for (int off = 8; off; off >>= 1)
                rm = fmaxf(rm, __shfl_xor_sync(0xffffffffu, rm, off));
            mnew[i] = fmaxf(mrow[i], rm);
            alpha[i] = expf(mrow[i] - mnew[i]);
        }
#pragma unroll
        for (int i = 0; i < 4; ++i) {
            float rs = 0.f;
#pragma unroll
            for (int j = 0; j < 4; ++j) {
                float p = expf(s[i][j] - mnew[i]);
                s[i][j] = p;
                rs += p;
            }
#pragma unroll
            for (int off = 8; off; off >>= 1)
                rs += __shfl_xor_sync(0xffffffffu, rs, off);
            lrow[i] = lrow[i] * alpha[i] + rs;
            mrow[i] = mnew[i];
#pragma unroll
            for (int j = 0; j < 4; ++j) o[i][j] *= alpha[i];
        }

        // Store P transposed: Ps[c][r]
#pragma unroll
        for (int i = 0; i < 4; ++i)
#pragma unroll
            for (int j = 0; j < 4; ++j)
                Ps[((tx << 2) + j) * 68 + (ty << 2) + i] = s[i][j];
        __syncthreads();

#pragma unroll 8
        for (int c = 0; c < 64; ++c) {
            float4 a = *(const float4*)(Ps + c * 68 + (ty << 2));
            float4 v = *(const float4*)(Vs + c * 68 + (tx << 2));
            float ar[4] = {a.x, a.y, a.z, a.w};
            float vr[4] = {v.x, v.y, v.z, v.w};
#pragma unroll
            for (int i = 0; i < 4; ++i)
#pragma unroll
                for (int j = 0; j < 4; ++j)
                    o[i][j] += ar[i] * vr[j];
        }
    }

#pragma unroll
    for (int i = 0; i < 4; ++i) {
        float inv = 1.0f / lrow[i];
        int r = q0 + (ty << 2) + i;
#pragma unroll
        for (int j = 0; j < 4; ++j) {
            int dcol = h * DKK + (tx << 2) + j;
            g_O[((size_t)b * SS + r) * DD + dcol] = o[i][j] * inv;
        }
    }
}

// ---------------------------------------------------------------------------
extern "C" void kernel_launch(void* const* d_in, const int* in_sizes, int n_in,
                              void* d_out, int out_size)
{
    const float* x  = (const float*)d_in[0];
    const int*   tp = (const int*)d_in[1];
    const float* Wq = (const float*)d_in[2];
    const float* bq = (const float*)d_in[3];
    const float* Wk = (const float*)d_in[4];
    const float* bk = (const float*)d_in[5];
    const float* Wv = (const float*)d_in[6];
    const float* bv = (const float*)d_in[7];
    const float* Wo = (const float*)d_in[8];
    const float* bo = (const float*)d_in[9];
    float* out = (float*)d_out;

    float *Qp, *Kp, *Vp, *Op;
    cudaGetSymbolAddress((void**)&Qp, g_Q);
    cudaGetSymbolAddress((void**)&Kp, g_K);
    cudaGetSymbolAddress((void**)&Vp, g_V);
    cudaGetSymbolAddress((void**)&Op, g_O);

    dim3 gGemm(DD / 64, MM / 64);  // (16, 64)
    sgemm_kernel<true><<<gGemm, 256>>>(x, Wq, bq, Qp);
    sgemm_kernel<true><<<gGemm, 256>>>(x, Wk, bk, Kp);
    sgemm_kernel<true><<<gGemm, 256>>>(x, Wv, bv, Vp);

    int ropeThreads = BB * HH * SS * (DKK / 2);
    rope_kernel<<<(ropeThreads + 255) / 256, 256>>>(tp);

    static int smem_set = 0;
    int smemBytes = 4 * 64 * 68 * (int)sizeof(float);  // 69632
    if (!smem_set) {
        cudaFuncSetAttribute(flash_kernel,
                             cudaFuncAttributeMaxDynamicSharedMemorySize,
                             smemBytes);
        smem_set = 1;
    }
    dim3 gFlash(SS / 64, HH, BB);  // (32, 16, 2)
    flash_kernel<<<gFlash, 256, smemBytes>>>();

    sgemm_kernel<false><<<gGemm, 256>>>(Op, Wo, bo, out);
}

// round 7
// speedup vs baseline: 1.6068x; 1.6068x over previous
#include <cuda_runtime.h>
#include <cuda_bf16.h>
#include <math.h>
#include <stdint.h>

// Problem constants
#define BB 2
#define SS 2048
#define DD 1024
#define HH 16
#define DKK 64
#define MM (BB * SS)          // 4096
#define SCALE 0.125f          // 1/sqrt(64)

// Scratch (allocation-free rule: __device__ globals)
__device__ float g_Q[BB * HH * SS * DKK];   // [B,H,S,DK]
__device__ float g_K[BB * HH * SS * DKK];
__device__ float g_V[BB * HH * SS * DKK];
__device__ float g_O[BB * SS * DD];         // [B,S,D]
__device__ __nv_bfloat16 g_xhi[MM * DD];
__device__ __nv_bfloat16 g_xlo[MM * DD];
__device__ __nv_bfloat16 g_ahi[MM * DD];    // O-proj input hi/lo
__device__ __nv_bfloat16 g_alo[MM * DD];
__device__ __nv_bfloat16 g_whi[DD * DD];    // W^T hi  (reused per-GEMM, stream-serial)
__device__ __nv_bfloat16 g_wlo[DD * DD];    // W^T lo

// ---------------------------------------------------------------------------
// fp32 -> bf16 hi/lo split (elementwise, for A operands)
// ---------------------------------------------------------------------------
__global__ __launch_bounds__(256) void convert_hl(
    const float* __restrict__ src, __nv_bfloat16* __restrict__ hi,
    __nv_bfloat16* __restrict__ lo, int n)
{
    int i = (blockIdx.x * blockDim.x + threadIdx.x) * 4;
    if (i >= n) return;
    float4 v = *(const float4*)(src + i);
    float f[4] = {v.x, v.y, v.z, v.w};
    __nv_bfloat16 h[4], l[4];
#pragma unroll
    for (int j = 0; j < 4; ++j) {
        h[j] = __float2bfloat16(f[j]);
        l[j] = __float2bfloat16(f[j] - __bfloat162float(h[j]));
    }
    *(uint2*)(hi + i) = *(uint2*)h;
    *(uint2*)(lo + i) = *(uint2*)l;
}

// ---------------------------------------------------------------------------
// W[k][n] (fp32) -> Wt[n][k] bf16 hi/lo (tiled transpose)
// ---------------------------------------------------------------------------
__global__ __launch_bounds__(256) void convert_w_t(
    const float* __restrict__ W, __nv_bfloat16* __restrict__ hi,
    __nv_bfloat16* __restrict__ lo)
{
    __shared__ float t[32][33];
    int tx = threadIdx.x, ty = threadIdx.y;
    int kin = blockIdx.y * 32;   // k range of this tile
    int nin = blockIdx.x * 32;   // n range of this tile
#pragma unroll
    for (int j = 0; j < 4; ++j)
        t[ty + j * 8][tx] = W[(size_t)(kin + ty + j * 8) * DD + nin + tx];
    __syncthreads();
#pragma unroll
    for (int j = 0; j < 4; ++j) {
        float v = t[tx][ty + j * 8];
        __nv_bfloat16 h = __float2bfloat16(v);
        __nv_bfloat16 l = __float2bfloat16(v - __bfloat162float(h));
        size_t o = (size_t)(nin + ty + j * 8) * DD + kin + tx;
        hi[o] = h;
        lo[o] = l;
    }
}

// ---------------------------------------------------------------------------
// HMMA helpers
// ---------------------------------------------------------------------------
__device__ __forceinline__ void mma16816(float* c, const uint32_t* a, const uint32_t* b)
{
    asm volatile(
        "mma.sync.aligned.m16n8k16.row.col.f32.bf16.bf16.f32 "
        "{%0,%1,%2,%3}, {%4,%5,%6,%7}, {%8,%9}, {%0,%1,%2,%3};"
        : "+f"(c[0]), "+f"(c[1]), "+f"(c[2]), "+f"(c[3])
        : "r"(a[0]), "r"(a[1]), "r"(a[2]), "r"(a[3]), "r"(b[0]), "r"(b[1]));
}

__device__ __forceinline__ uint32_t s2u(const void* p) {
    uint32_t a;
    asm("{ .reg .u64 t; cvta.to.shared.u64 t, %1; cvt.u32.u64 %0, t; }"
        : "=r"(a) : "l"(p));
    return a;
}

__device__ __forceinline__ void cp16(uint32_t dst, const void* src) {
    asm volatile("cp.async.cg.shared.global [%0], [%1], 16;" :: "r"(dst), "l"(src));
}
#define CP_COMMIT() asm volatile("cp.async.commit_group;" ::: "memory")
#define CP_WAIT1()  asm volatile("cp.async.wait_group 1;" ::: "memory")

// ---------------------------------------------------------------------------
// bf16x3 HMMA GEMM: C[4096,1024] = A @ W + bias
// CTA 128x128, 8 warps (2x4 -> each 64x32), BK=32, cp.async double buffer.
// A smem: [m][k] pitch 80B. B smem: [n][k] pitch 80B (W pre-transposed).
// Stage: Ahi(10240) Alo(10240) Bhi(10240) Blo(10240) = 40960B; x2 = 81920B.
// ---------------------------------------------------------------------------
#define GEMM_SMEM 81920

template <bool HEAD_LAYOUT>
__global__ __launch_bounds__(256, 2) void mma_gemm(
    const __nv_bfloat16* __restrict__ Ahi, const __nv_bfloat16* __restrict__ Alo,
    const __nv_bfloat16* __restrict__ Bhi, const __nv_bfloat16* __restrict__ Blo,
    const float* __restrict__ bias, float* __restrict__ out)
{
    extern __shared__ char smem[];
    const uint32_t smem_u = s2u(smem);
    const int tid = threadIdx.x;
    const int lane = tid & 31;
    const int wid = tid >> 5;
    const int g = lane >> 2;       // groupID
    const int tg = lane & 3;       // thread-in-group
    const int warp_m = wid & 1;    // 0..1 (x64 rows)
    const int warp_n = wid >> 1;   // 0..3 (x32 cols)
    const int n0 = blockIdx.x * 128;
    const int m0 = blockIdx.y * 128;

    float acc[4][4][4] = {};

    const int r_ = tid >> 2, c4 = tid & 3;   // loader decomposition (128 rows x 4 vecs)

    // Stage loader: 2 uint4 per buffer per thread
    auto load_stage = [&](int st, int kc) {
        const int k0 = kc * 32;
        const uint32_t sb = smem_u + st * 40960;
        {   // A tile: 128 rows x 32 bf16
            uint32_t d = sb + r_ * 80 + c4 * 16;
            size_t gsrc = (size_t)(m0 + r_) * DD + k0 + c4 * 8;
            cp16(d, Ahi + gsrc);
            cp16(d + 10240, Alo + gsrc);
            d += 64 * 80;  gsrc += (size_t)64 * DD;
            cp16(d, Ahi + gsrc);
            cp16(d + 10240, Alo + gsrc);
        }
        {   // B tile: 128 n-rows x 32 k
            uint32_t d = sb + 20480 + r_ * 80 + c4 * 16;
            size_t gsrc = (size_t)(n0 + r_) * DD + k0 + c4 * 8;
            cp16(d, Bhi + gsrc);
            cp16(d + 10240, Blo + gsrc);
            d += 64 * 80;  gsrc += (size_t)64 * DD;
            cp16(d, Bhi + gsrc);
            cp16(d + 10240, Blo + gsrc);
        }
    };

    load_stage(0, 0); CP_COMMIT();
    load_stage(1, 1); CP_COMMIT();

    for (int kc = 0; kc < 32; ++kc) {
        const int st = kc & 1;
        CP_WAIT1();
        __syncthreads();

        const char* sA = smem + st * 40960 + (warp_m * 64) * 80;
        const char* sB = smem + st * 40960 + 20480 + (warp_n * 32) * 80;

#pragma unroll
        for (int ks = 0; ks < 2; ++ks) {
            const int kb = ks * 32 + tg * 4;

            uint32_t bh[4][2], ah[4][4];
#pragma unroll
            for (int nt = 0; nt < 4; ++nt) {
                const char* p = sB + (nt * 8 + g) * 80 + kb;
                bh[nt][0] = *(const uint32_t*)p;
                bh[nt][1] = *(const uint32_t*)(p + 16);
            }
#pragma unroll
            for (int mt = 0; mt < 4; ++mt) {
                const char* p = sA + (mt * 16 + g) * 80 + kb;
                ah[mt][0] = *(const uint32_t*)p;
                ah[mt][1] = *(const uint32_t*)(p + 640);
                ah[mt][2] = *(const uint32_t*)(p + 16);
                ah[mt][3] = *(const uint32_t*)(p + 656);
            }
#pragma unroll
            for (int mt = 0; mt < 4; ++mt)
#pragma unroll
                for (int nt = 0; nt < 4; ++nt)
                    mma16816(acc[mt][nt], ah[mt], bh[nt]);

            uint32_t bl[4][2];
#pragma unroll
            for (int nt = 0; nt < 4; ++nt) {
                const char* p = sB + 10240 + (nt * 8 + g) * 80 + kb;
                bl[nt][0] = *(const uint32_t*)p;
                bl[nt][1] = *(const uint32_t*)(p + 16);
            }
#pragma unroll
            for (int mt = 0; mt < 4; ++mt)
#pragma unroll
                for (int nt = 0; nt < 4; ++nt)
                    mma16816(acc[mt][nt], ah[mt], bl[nt]);

            uint32_t al[4][4];
#pragma unroll
            for (int mt = 0; mt < 4; ++mt) {
                const char* p = sA + 10240 + (mt * 16 + g) * 80 + kb;
                al[mt][0] = *(const uint32_t*)p;
                al[mt][1] = *(const uint32_t*)(p + 640);
                al[mt][2] = *(const uint32_t*)(p + 16);
                al[mt][3] = *(const uint32_t*)(p + 656);
            }
#pragma unroll
            for (int mt = 0; mt < 4; ++mt)
#pragma unroll
                for (int nt = 0; nt < 4; ++nt)
                    mma16816(acc[mt][nt], al[mt], bh[nt]);
        }

        __syncthreads();
        if (kc + 2 < 32) load_stage(st, kc + 2);
        CP_COMMIT();
    }

    // Epilogue
#pragma unroll
    for (int mt = 0; mt < 4; ++mt) {
        const int m = m0 + warp_m * 64 + mt * 16 + g;
#pragma unroll
        for (int nt = 0; nt < 4; ++nt) {
            const int nc = n0 + warp_n * 32 + nt * 8 + tg * 2;
            const float b0 = __ldg(bias + nc), b1 = __ldg(bias + nc + 1);
            float2 v0 = {acc[mt][nt][0] + b0, acc[mt][nt][1] + b1};
            float2 v1 = {acc[mt][nt][2] + b0, acc[mt][nt][3] + b1};
            if (HEAD_LAYOUT) {
                const int h = nc >> 6, dk = nc & 63;
                const int b_ = m >> 11, s = m & 2047;
                size_t base = (((size_t)(b_ * HH + h) * SS) + s) * DKK + dk;
                *(float2*)(out + base) = v0;
                *(float2*)(out + base + 8 * DKK) = v1;
            } else {
                *(float2*)(out + (size_t)m * DD + nc) = v0;
                *(float2*)(out + (size_t)(m + 8) * DD + nc) = v1;
            }
        }
    }
}

// ---------------------------------------------------------------------------
// RoPE on g_Q and g_K in-place. inv_freq table (fp64 exp) computed once per
// block into smem; angle multiply + sincos all fp32 (matches JAX fp32 path).
// ---------------------------------------------------------------------------
__global__ __launch_bounds__(256) void rope_kernel(const int* __restrict__ pos)
{
    __shared__ float invs[32];
    if (threadIdx.x < 32)
        invs[threadIdx.x] =
            (float)exp(-(double)threadIdx.x * 0.28782313662425575);
    __syncthreads();

    int idx = blockIdx.x * blockDim.x + threadIdx.x;
    if (idx >= BB * HH * SS * (DKK / 2)) return;
    int i = idx & 31;
    int s = (idx >> 5) & 2047;
    int h = (idx >> 16) & 15;
    int b = idx >> 20;

    int p = pos[b * SS + s];
    float ang = (float)p * invs[i];
    float c, sn;
    sincosf(ang, &sn, &c);

    size_t base = (((size_t)(b * HH + h) * SS) + s) * DKK + 2 * i;
    float q0 = g_Q[base], q1 = g_Q[base + 1];
    g_Q[base]     = q0 * c - q1 * sn;
    g_Q[base + 1] = q0 * sn + q1 * c;
    float k0 = g_K[base], k1 = g_K[base + 1];
    g_K[base]     = k0 * c - k1 * sn;
    g_K[base + 1] = k0 * sn + k1 * c;
}

// ---------------------------------------------------------------------------
// Flash attention (fp32, causal) — unchanged from passing R5 kernel.
// ---------------------------------------------------------------------------
__global__ __launch_bounds__(256) void flash_kernel()
{
    extern __shared__ float sm[];
    float* Qs = sm;
    float* Ks = sm + 64 * 68;
    float* Vs = sm + 2 * 64 * 68;
    float* Ps = sm + 3 * 64 * 68;

    const int qt = (int)gridDim.x - 1 - (int)blockIdx.x;
    const int h = blockIdx.y;
    const int b = blockIdx.z;
    const int q0 = qt * 64;
    const int tid = threadIdx.x;
    const int tx = tid & 15;
    const int ty = tid >> 4;

    const float* Qg = g_Q + ((size_t)(b * HH + h) * SS) * DKK;
    const float* Kg = g_K + ((size_t)(b * HH + h) * SS) * DKK;
    const float* Vg = g_V + ((size_t)(b * HH + h) * SS) * DKK;

    for (int idx = tid; idx < 4096; idx += 256) {
        int r = idx >> 6, d = idx & 63;
        Qs[d * 68 + r] = Qg[(size_t)(q0 + r) * DKK + d];
    }

    float o[4][4] = {};
    float mrow[4] = {-1e30f, -1e30f, -1e30f, -1e30f};
    float lrow[4] = {};

    const int nTiles = qt + 1;
    for (int t = 0; t < nTiles; ++t) {
        const int j0 = t * 64;
        __syncthreads();
        for (int idx = tid; idx < 4096; idx += 256) {
            int r = idx >> 6, d = idx & 63;
            Ks[d * 68 + r] = Kg[(size_t)(j0 + r) * DKK + d];
            Vs[r * 68 + d] = Vg[(size_t)(j0 + r) * DKK + d];
        }
        __syncthreads();

        float s[4][4] = {};
#pragma unroll 8
        for (int d = 0; d < 64; ++d) {
            float4 a = *(const float4*)(Qs + d * 68 + (ty << 2));
            float4 bb = *(const float4*)(Ks + d * 68 + (tx << 2));
            float ar[4] = {a.x, a.y, a.z, a.w};
            float br[4] = {bb.x, bb.y, bb.z, bb.w};
#pragma unroll
            for (int i = 0; i < 4; ++i)
#pragma unroll
                for (int j = 0; j < 4; ++j)
                    s[i][j] += ar[i] * br[j];
        }

        const bool diag = (t == qt);
#pragma unroll
        for (int i = 0; i < 4; ++i)
#pragma unroll
            for (int j = 0; j < 4; ++j) {
                float v = s[i][j] * SCALE;
                if (diag && ((tx << 2) + j) > ((ty << 2) + i)) v = -1e30f;
                s[i][j] = v;
            }

        float mnew[4], alpha[4];
#pragma unroll
        for (int i = 0; i < 4; ++i) {
            float rm = fmaxf(fmaxf(s[i][0], s[i][1]), fmaxf(s[i][2], s[i][3]));
#pragma unroll
            for (int off = 8; off; off >>= 1)
                rm = fmaxf(rm, __shfl_xor_sync(0xffffffffu, rm, off));
            mnew[i] = fmaxf(mrow[i], rm);
            alpha[i] = expf(mrow[i] - mnew[i]);
        }
#pragma unroll
        for (int i = 0; i < 4; ++i) {
            float rs = 0.f;
#pragma unroll
            for (int j = 0; j < 4; ++j) {
                float p = expf(s[i][j] - mnew[i]);
                s[i][j] = p;
                rs += p;
            }
#pragma unroll
            for (int off = 8; off; off >>= 1)
                rs += __shfl_xor_sync(0xffffffffu, rs, off);
            lrow[i] = lrow[i] * alpha[i] + rs;
            mrow[i] = mnew[i];
#pragma unroll
            for (int j = 0; j < 4; ++j) o[i][j] *= alpha[i];
        }

#pragma unroll
        for (int i = 0; i < 4; ++i)
#pragma unroll
            for (int j = 0; j < 4; ++j)
                Ps[((tx << 2) + j) * 68 + (ty << 2) + i] = s[i][j];
        __syncthreads();

#pragma unroll 8
        for (int c = 0; c < 64; ++c) {
            float4 a = *(const float4*)(Ps + c * 68 + (ty << 2));
            float4 v = *(const float4*)(Vs + c * 68 + (tx << 2));
            float ar[4] = {a.x, a.y, a.z, a.w};
            float vr[4] = {v.x, v.y, v.z, v.w};
#pragma unroll
            for (int i = 0; i < 4; ++i)
#pragma unroll
                for (int j = 0; j < 4; ++j)
                    o[i][j] += ar[i] * vr[j];
        }
    }

#pragma unroll
    for (int i = 0; i < 4; ++i) {
        float inv = 1.0f / lrow[i];
        int r = q0 + (ty << 2) + i;
#pragma unroll
        for (int j = 0; j < 4; ++j) {
            int dcol = h * DKK + (tx << 2) + j;
            g_O[((size_t)b * SS + r) * DD + dcol] = o[i][j] * inv;
        }
    }
}

// ---------------------------------------------------------------------------
extern "C" void kernel_launch(void* const* d_in, const int* in_sizes, int n_in,
                              void* d_out, int out_size)
{
    const float* x  = (const float*)d_in[0];
    const int*   tp = (const int*)d_in[1];
    const float* Wq = (const float*)d_in[2];
    const float* bq = (const float*)d_in[3];
    const float* Wk = (const float*)d_in[4];
    const float* bk = (const float*)d_in[5];
    const float* Wv = (const float*)d_in[6];
    const float* bv = (const float*)d_in[7];
    const float* Wo = (const float*)d_in[8];
    const float* bo = (const float*)d_in[9];
    float* out = (float*)d_out;

    float *Qp, *Kp, *Vp, *Op;
    __nv_bfloat16 *xhi, *xlo, *ahi, *alo, *whi, *wlo;
    cudaGetSymbolAddress((void**)&Qp, g_Q);
    cudaGetSymbolAddress((void**)&Kp, g_K);
    cudaGetSymbolAddress((void**)&Vp, g_V);
    cudaGetSymbolAddress((void**)&Op, g_O);
    cudaGetSymbolAddress((void**)&xhi, g_xhi);
    cudaGetSymbolAddress((void**)&xlo, g_xlo);
    cudaGetSymbolAddress((void**)&ahi, g_ahi);
    cudaGetSymbolAddress((void**)&alo, g_alo);
    cudaGetSymbolAddress((void**)&whi, g_whi);
    cudaGetSymbolAddress((void**)&wlo, g_wlo);

    static int attr_set = 0;
    if (!attr_set) {
        cudaFuncSetAttribute(mma_gemm<true>,
                             cudaFuncAttributeMaxDynamicSharedMemorySize, GEMM_SMEM);
        cudaFuncSetAttribute(mma_gemm<false>,
                             cudaFuncAttributeMaxDynamicSharedMemorySize, GEMM_SMEM);
        cudaFuncSetAttribute(flash_kernel,
                             cudaFuncAttributeMaxDynamicSharedMemorySize,
                             4 * 64 * 68 * (int)sizeof(float));
        attr_set = 1;
    }

    const int nX = MM * DD;          // 4,194,304
    dim3 gW(DD / 32, DD / 32);       // transpose-convert grid
    dim3 bW(32, 8);
    dim3 gGemm(DD / 128, MM / 128);  // (8, 32)

    // x -> hi/lo once (shared by Q/K/V projections)
    convert_hl<<<nX / 4 / 256, 256>>>(x, xhi, xlo, nX);

    convert_w_t<<<gW, bW>>>(Wq, whi, wlo);
    mma_gemm<true><<<gGemm, 256, GEMM_SMEM>>>(xhi, xlo, whi, wlo, bq, Qp);
    convert_w_t<<<gW, bW>>>(Wk, whi, wlo);
    mma_gemm<true><<<gGemm, 256, GEMM_SMEM>>>(xhi, xlo, whi, wlo, bk, Kp);
    convert_w_t<<<gW, bW>>>(Wv, whi, wlo);
    mma_gemm<true><<<gGemm, 256, GEMM_SMEM>>>(xhi, xlo, whi, wlo, bv, Vp);

    int ropeThreads = BB * HH * SS * (DKK / 2);
    rope_kernel<<<(ropeThreads + 255) / 256, 256>>>(tp);

    dim3 gFlash(SS / 64, HH, BB);
    flash_kernel<<<gFlash, 256, 4 * 64 * 68 * sizeof(float)>>>();

    convert_hl<<<nX / 4 / 256, 256>>>(Op, ahi, alo, nX);
    convert_w_t<<<gW, bW>>>(Wo, whi, wlo);
    mma_gemm<false><<<gGemm, 256, GEMM_SMEM>>>(ahi, alo, whi, wlo, bo, out);
}

// round 8
// speedup vs baseline: 2.7040x; 1.6828x over previous
#include <cuda_runtime.h>
#include <cuda_bf16.h>
#include <math.h>
#include <stdint.h>

// Problem constants
#define BB 2
#define SS 2048
#define DD 1024
#define HH 16
#define DKK 64
#define MM (BB * SS)          // 4096
#define SCALE 0.125f          // 1/sqrt(64)

// Scratch (allocation-free rule: __device__ globals)
__device__ float g_Q[BB * HH * SS * DKK];   // [B,H,S,DK] fp32 (pre-RoPE)
__device__ float g_K[BB * HH * SS * DKK];
__device__ __nv_bfloat16 g_Qhi[BB * HH * SS * DKK];  // post-RoPE hi/lo
__device__ __nv_bfloat16 g_Qlo[BB * HH * SS * DKK];
__device__ __nv_bfloat16 g_Khi[BB * HH * SS * DKK];
__device__ __nv_bfloat16 g_Klo[BB * HH * SS * DKK];
__device__ __nv_bfloat16 g_Vthi[BB * HH * DKK * SS]; // V transposed [b,h,dk,s]
__device__ __nv_bfloat16 g_Vtlo[BB * HH * DKK * SS];
__device__ __nv_bfloat16 g_xhi[MM * DD];
__device__ __nv_bfloat16 g_xlo[MM * DD];
__device__ __nv_bfloat16 g_ahi[MM * DD];    // attention output hi/lo (O-proj input)
__device__ __nv_bfloat16 g_alo[MM * DD];
__device__ __nv_bfloat16 g_whi[DD * DD];    // W^T hi (reused per-GEMM, stream-serial)
__device__ __nv_bfloat16 g_wlo[DD * DD];

// ---------------------------------------------------------------------------
// Helpers
// ---------------------------------------------------------------------------
__device__ __forceinline__ uint32_t s2u(const void* p) {
    uint32_t a;
    asm("{ .reg .u64 t; cvta.to.shared.u64 t, %1; cvt.u32.u64 %0, t; }"
        : "=r"(a) : "l"(p));
    return a;
}
__device__ __forceinline__ void cp16(uint32_t dst, const void* src) {
    asm volatile("cp.async.cg.shared.global [%0], [%1], 16;" :: "r"(dst), "l"(src));
}
#define CP_COMMIT() asm volatile("cp.async.commit_group;" ::: "memory")
#define CP_WAIT1()  asm volatile("cp.async.wait_group 1;" ::: "memory")

__device__ __forceinline__ void mma16816(float* c, const uint32_t* a, const uint32_t* b)
{
    asm volatile(
        "mma.sync.aligned.m16n8k16.row.col.f32.bf16.bf16.f32 "
        "{%0,%1,%2,%3}, {%4,%5,%6,%7}, {%8,%9}, {%0,%1,%2,%3};"
        : "+f"(c[0]), "+f"(c[1]), "+f"(c[2]), "+f"(c[3])
        : "r"(a[0]), "r"(a[1]), "r"(a[2]), "r"(a[3]), "r"(b[0]), "r"(b[1]));
}

__device__ __forceinline__ uint32_t pack_bf2(float a, float b) {
    __nv_bfloat162 t = __floats2bfloat162_rn(a, b);
    return *(uint32_t*)&t;
}

// ---------------------------------------------------------------------------
// fp32 -> bf16 hi/lo split (elementwise)
// ---------------------------------------------------------------------------
__global__ __launch_bounds__(256) void convert_hl(
    const float* __restrict__ src, __nv_bfloat16* __restrict__ hi,
    __nv_bfloat16* __restrict__ lo, int n)
{
    int i = (blockIdx.x * blockDim.x + threadIdx.x) * 4;
    if (i >= n) return;
    float4 v = *(const float4*)(src + i);
    float f[4] = {v.x, v.y, v.z, v.w};
    __nv_bfloat16 h[4], l[4];
#pragma unroll
    for (int j = 0; j < 4; ++j) {
        h[j] = __float2bfloat16(f[j]);
        l[j] = __float2bfloat16(f[j] - __bfloat162float(h[j]));
    }
    *(uint2*)(hi + i) = *(uint2*)h;
    *(uint2*)(lo + i) = *(uint2*)l;
}

// ---------------------------------------------------------------------------
// W[k][n] (fp32) -> Wt[n][k] bf16 hi/lo (tiled transpose)
// ---------------------------------------------------------------------------
__global__ __launch_bounds__(256) void convert_w_t(
    const float* __restrict__ W, __nv_bfloat16* __restrict__ hi,
    __nv_bfloat16* __restrict__ lo)
{
    __shared__ float t[32][33];
    int tx = threadIdx.x, ty = threadIdx.y;
    int kin = blockIdx.y * 32;
    int nin = blockIdx.x * 32;
#pragma unroll
    for (int j = 0; j < 4; ++j)
        t[ty + j * 8][tx] = W[(size_t)(kin + ty + j * 8) * DD + nin + tx];
    __syncthreads();
#pragma unroll
    for (int j = 0; j < 4; ++j) {
        float v = t[tx][ty + j * 8];
        __nv_bfloat16 h = __float2bfloat16(v);
        __nv_bfloat16 l = __float2bfloat16(v - __bfloat162float(h));
        size_t o = (size_t)(nin + ty + j * 8) * DD + kin + tx;
        hi[o] = h;
        lo[o] = l;
    }
}

// ---------------------------------------------------------------------------
// bf16x3 HMMA GEMM: C[4096,1024] = A @ W + bias
// CTA 128x128, 8 warps (2x4 -> each 64x32), BK=32, cp.async double buffer.
// MODE 0: fp32 out [m][n].  MODE 1: fp32 out head layout [b,h,s,dk].
// MODE 2: bf16 hi/lo out transposed [b,h,dk,s].
// ---------------------------------------------------------------------------
#define GEMM_SMEM 81920

template <int MODE>
__global__ __launch_bounds__(256, 2) void mma_gemm(
    const __nv_bfloat16* __restrict__ Ahi, const __nv_bfloat16* __restrict__ Alo,
    const __nv_bfloat16* __restrict__ Bhi, const __nv_bfloat16* __restrict__ Blo,
    const float* __restrict__ bias, float* __restrict__ out,
    __nv_bfloat16* __restrict__ ohi, __nv_bfloat16* __restrict__ olo)
{
    extern __shared__ char smem[];
    const uint32_t smem_u = s2u(smem);
    const int tid = threadIdx.x;
    const int lane = tid & 31;
    const int wid = tid >> 5;
    const int g = lane >> 2;
    const int tg = lane & 3;
    const int warp_m = wid & 1;
    const int warp_n = wid >> 1;
    const int n0 = blockIdx.x * 128;
    const int m0 = blockIdx.y * 128;

    float acc[4][4][4] = {};

    const int r_ = tid >> 2, c4 = tid & 3;

    auto load_stage = [&](int st, int kc) {
        const int k0 = kc * 32;
        const uint32_t sb = smem_u + st * 40960;
        {
            uint32_t d = sb + r_ * 80 + c4 * 16;
            size_t gsrc = (size_t)(m0 + r_) * DD + k0 + c4 * 8;
            cp16(d, Ahi + gsrc);
            cp16(d + 10240, Alo + gsrc);
            d += 64 * 80;  gsrc += (size_t)64 * DD;
            cp16(d, Ahi + gsrc);
            cp16(d + 10240, Alo + gsrc);
        }
        {
            uint32_t d = sb + 20480 + r_ * 80 + c4 * 16;
            size_t gsrc = (size_t)(n0 + r_) * DD + k0 + c4 * 8;
            cp16(d, Bhi + gsrc);
            cp16(d + 10240, Blo + gsrc);
            d += 64 * 80;  gsrc += (size_t)64 * DD;
            cp16(d, Bhi + gsrc);
            cp16(d + 10240, Blo + gsrc);
        }
    };

    load_stage(0, 0); CP_COMMIT();
    load_stage(1, 1); CP_COMMIT();

    for (int kc = 0; kc < 32; ++kc) {
        const int st = kc & 1;
        CP_WAIT1();
        __syncthreads();

        const char* sA = smem + st * 40960 + (warp_m * 64) * 80;
        const char* sB = smem + st * 40960 + 20480 + (warp_n * 32) * 80;

#pragma unroll
        for (int ks = 0; ks < 2; ++ks) {
            const int kb = ks * 32 + tg * 4;

            uint32_t bh[4][2], ah[4][4];
#pragma unroll
            for (int nt = 0; nt < 4; ++nt) {
                const char* p = sB + (nt * 8 + g) * 80 + kb;
                bh[nt][0] = *(const uint32_t*)p;
                bh[nt][1] = *(const uint32_t*)(p + 16);
            }
#pragma unroll
            for (int mt = 0; mt < 4; ++mt) {
                const char* p = sA + (mt * 16 + g) * 80 + kb;
                ah[mt][0] = *(const uint32_t*)p;
                ah[mt][1] = *(const uint32_t*)(p + 640);
                ah[mt][2] = *(const uint32_t*)(p + 16);
                ah[mt][3] = *(const uint32_t*)(p + 656);
            }
#pragma unroll
            for (int mt = 0; mt < 4; ++mt)
#pragma unroll
                for (int nt = 0; nt < 4; ++nt)
                    mma16816(acc[mt][nt], ah[mt], bh[nt]);

            uint32_t bl[4][2];
#pragma unroll
            for (int nt = 0; nt < 4; ++nt) {
                const char* p = sB + 10240 + (nt * 8 + g) * 80 + kb;
                bl[nt][0] = *(const uint32_t*)p;
                bl[nt][1] = *(const uint32_t*)(p + 16);
            }
#pragma unroll
            for (int mt = 0; mt < 4; ++mt)
#pragma unroll
                for (int nt = 0; nt < 4; ++nt)
                    mma16816(acc[mt][nt], ah[mt], bl[nt]);

            uint32_t al[4][4];
#pragma unroll
            for (int mt = 0; mt < 4; ++mt) {
                const char* p = sA + 10240 + (mt * 16 + g) * 80 + kb;
                al[mt][0] = *(const uint32_t*)p;
                al[mt][1] = *(const uint32_t*)(p + 640);
                al[mt][2] = *(const uint32_t*)(p + 16);
                al[mt][3] = *(const uint32_t*)(p + 656);
            }
#pragma unroll
            for (int mt = 0; mt < 4; ++mt)
#pragma unroll
                for (int nt = 0; nt < 4; ++nt)
                    mma16816(acc[mt][nt], al[mt], bh[nt]);
        }

        __syncthreads();
        if (kc + 2 < 32) load_stage(st, kc + 2);
        CP_COMMIT();
    }

    // Epilogue
#pragma unroll
    for (int mt = 0; mt < 4; ++mt) {
        const int m = m0 + warp_m * 64 + mt * 16 + g;
#pragma unroll
        for (int nt = 0; nt < 4; ++nt) {
            const int nc = n0 + warp_n * 32 + nt * 8 + tg * 2;
            const float b0 = __ldg(bias + nc), b1 = __ldg(bias + nc + 1);
            float v00 = acc[mt][nt][0] + b0, v01 = acc[mt][nt][1] + b1;
            float v10 = acc[mt][nt][2] + b0, v11 = acc[mt][nt][3] + b1;
            if (MODE == 1) {
                const int h = nc >> 6, dk = nc & 63;
                const int b_ = m >> 11, s = m & 2047;
                size_t base = (((size_t)(b_ * HH + h) * SS) + s) * DKK + dk;
                *(float2*)(out + base) = make_float2(v00, v01);
                *(float2*)(out + base + 8 * DKK) = make_float2(v10, v11);
            } else if (MODE == 2) {
                // V: bf16 hi/lo, transposed [b,h,dk,s]
                const int h = nc >> 6, dk = nc & 63;
                const int b_ = m >> 11, s = m & 2047;
                size_t base = (((size_t)(b_ * HH + h) * DKK) + dk) * SS + s;
                float vv[4] = {v00, v01, v10, v11};
                size_t off[4] = {base, base + SS, base + 8, base + SS + 8};
#pragma unroll
                for (int e = 0; e < 4; ++e) {
                    __nv_bfloat16 hh = __float2bfloat16(vv[e]);
                    ohi[off[e]] = hh;
                    olo[off[e]] = __float2bfloat16(vv[e] - __bfloat162float(hh));
                }
            } else {
                *(float2*)(out + (size_t)m * DD + nc) = make_float2(v00, v01);
                *(float2*)(out + (size_t)(m + 8) * DD + nc) = make_float2(v10, v11);
            }
        }
    }
}

// ---------------------------------------------------------------------------
// RoPE: read fp32 g_Q/g_K, rotate, write bf16 hi/lo Q/K.
// ---------------------------------------------------------------------------
__global__ __launch_bounds__(256) void rope_kernel(const int* __restrict__ pos)
{
    __shared__ float invs[32];
    if (threadIdx.x < 32)
        invs[threadIdx.x] = (float)exp(-(double)threadIdx.x * 0.28782313662425575);
    __syncthreads();

    int idx = blockIdx.x * blockDim.x + threadIdx.x;
    if (idx >= BB * HH * SS * (DKK / 2)) return;
    int i = idx & 31;
    int s = (idx >> 5) & 2047;
    int h = (idx >> 16) & 15;
    int b = idx >> 20;

    int p = pos[b * SS + s];
    float ang = (float)p * invs[i];
    float c, sn;
    sincosf(ang, &sn, &c);

    size_t base = (((size_t)(b * HH + h) * SS) + s) * DKK + 2 * i;
    float q0 = g_Q[base], q1 = g_Q[base + 1];
    float qr0 = q0 * c - q1 * sn;
    float qr1 = q0 * sn + q1 * c;
    float k0 = g_K[base], k1 = g_K[base + 1];
    float kr0 = k0 * c - k1 * sn;
    float kr1 = k0 * sn + k1 * c;

    __nv_bfloat162 qh = __floats2bfloat162_rn(qr0, qr1);
    *(uint32_t*)(g_Qhi + base) = *(uint32_t*)&qh;
    __nv_bfloat162 ql = __floats2bfloat162_rn(qr0 - __bfloat162float(qh.x),
                                              qr1 - __bfloat162float(qh.y));
    *(uint32_t*)(g_Qlo + base) = *(uint32_t*)&ql;
    __nv_bfloat162 kh = __floats2bfloat162_rn(kr0, kr1);
    *(uint32_t*)(g_Khi + base) = *(uint32_t*)&kh;
    __nv_bfloat162 kl = __floats2bfloat162_rn(kr0 - __bfloat162float(kh.x),
                                              kr1 - __bfloat162float(kh.y));
    *(uint32_t*)(g_Klo + base) = *(uint32_t*)&kl;
}

// ---------------------------------------------------------------------------
// Flash attention with HMMA (bf16x3 split for QK and PV).
// CTA = 64 query rows of one (b,h); 128 threads, 4 warps (16 rows each).
// K/Vt tiles double-buffered in smem (pitch 144B, conflict-free frag loads).
// Output written as bf16 hi/lo directly into g_ahi/g_alo.
// ---------------------------------------------------------------------------
#define FL_PITCH 144
#define FL_TILE (64 * FL_PITCH)     // 9216
#define FL_STAGE (4 * FL_TILE)      // 36864
#define FL_SMEM (2 * FL_STAGE)      // 73728

__global__ __launch_bounds__(128) void flash_mma()
{
    extern __shared__ char smem[];
    const int qt = (int)gridDim.x - 1 - (int)blockIdx.x;  // heavy first
    const int h = blockIdx.y;
    const int b = blockIdx.z;
    const int q0 = qt * 64;
    const int tid = threadIdx.x;
    const int lane = tid & 31;
    const int w = tid >> 5;
    const int g = lane >> 2;
    const int tg = lane & 3;

    const size_t bh = (size_t)(b * HH + h);
    const __nv_bfloat16* Qhi = g_Qhi + bh * SS * DKK;
    const __nv_bfloat16* Qlo = g_Qlo + bh * SS * DKK;
    const __nv_bfloat16* Khi = g_Khi + bh * SS * DKK;
    const __nv_bfloat16* Klo = g_Klo + bh * SS * DKK;
    const __nv_bfloat16* Vthi = g_Vthi + bh * DKK * SS;
    const __nv_bfloat16* Vtlo = g_Vtlo + bh * DKK * SS;

    // Q fragments (persistent): row block = q0 + 16w
    const int qrow = q0 + w * 16 + g;
    uint32_t qh[4][4], ql[4][4];
#pragma unroll
    for (int kc = 0; kc < 4; ++kc) {
        size_t p0 = (size_t)qrow * DKK + kc * 16 + tg * 2;
        qh[kc][0] = *(const uint32_t*)(Qhi + p0);
        qh[kc][1] = *(const uint32_t*)(Qhi + p0 + 8 * DKK);
        qh[kc][2] = *(const uint32_t*)(Qhi + p0 + 8);
        qh[kc][3] = *(const uint32_t*)(Qhi + p0 + 8 * DKK + 8);
        ql[kc][0] = *(const uint32_t*)(Qlo + p0);
        ql[kc][1] = *(const uint32_t*)(Qlo + p0 + 8 * DKK);
        ql[kc][2] = *(const uint32_t*)(Qlo + p0 + 8);
        ql[kc][3] = *(const uint32_t*)(Qlo + p0 + 8 * DKK + 8);
    }

    auto load_stage = [&](int st, int t) {
        const int j0 = t * 64;
        char* sb = smem + st * FL_STAGE;
#pragma unroll
        for (int i = 0; i < 4; ++i) {
            int v = i * 128 + tid;
            int r = v >> 3, c = v & 7;
            uint32_t d = s2u(sb + r * FL_PITCH + c * 16);
            size_t ksrc = (size_t)(j0 + r) * DKK + c * 8;
            cp16(d, Khi + ksrc);
            cp16(d + FL_TILE, Klo + ksrc);
            size_t vsrc = (size_t)r * SS + j0 + c * 8;
            cp16(d + 2 * FL_TILE, Vthi + vsrc);
            cp16(d + 3 * FL_TILE, Vtlo + vsrc);
        }
    };

    float o[8][4] = {};
    float m_g = -1e30f, m_g8 = -1e30f;
    float l_g = 0.f, l_g8 = 0.f;

    const int nT = qt + 1;
    load_stage(0, 0); CP_COMMIT();
    if (nT > 1) load_stage(1, 1);
    CP_COMMIT();

    for (int t = 0; t < nT; ++t) {
        const int st = t & 1;
        CP_WAIT1();
        __syncthreads();

        const char* sK  = smem + st * FL_STAGE;
        const char* sKl = sK + FL_TILE;
        const char* sV  = sK + 2 * FL_TILE;
        const char* sVl = sK + 3 * FL_TILE;
        const int j0 = t * 64;

        // ---- S = Q K^T (bf16x3) ----
        float s[8][4] = {};
#pragma unroll
        for (int kc = 0; kc < 4; ++kc) {
            const int kb = kc * 32 + tg * 4;
            uint32_t kh[8][2], kl[8][2];
#pragma unroll
            for (int nf = 0; nf < 8; ++nf) {
                const char* p = sK + (nf * 8 + g) * FL_PITCH + kb;
                kh[nf][0] = *(const uint32_t*)p;
                kh[nf][1] = *(const uint32_t*)(p + 16);
                const char* p2 = sKl + (nf * 8 + g) * FL_PITCH + kb;
                kl[nf][0] = *(const uint32_t*)p2;
                kl[nf][1] = *(const uint32_t*)(p2 + 16);
            }
#pragma unroll
            for (int nf = 0; nf < 8; ++nf) {
                mma16816(s[nf], qh[kc], kh[nf]);
                mma16816(s[nf], qh[kc], kl[nf]);
                mma16816(s[nf], ql[kc], kh[nf]);
            }
        }

        // ---- scale + causal mask ----
        const bool diag = (t == qt);
#pragma unroll
        for (int nf = 0; nf < 8; ++nf) {
#pragma unroll
            for (int e = 0; e < 4; ++e) {
                float v = s[nf][e] * SCALE;
                if (diag) {
                    int col = j0 + nf * 8 + tg * 2 + (e & 1);
                    int row = qrow + ((e >> 1) << 3);
                    if (col > row) v = -1e30f;
                }
                s[nf][e] = v;
            }
        }

        // ---- online softmax ----
        float tm_g = -1e30f, tm_g8 = -1e30f;
#pragma unroll
        for (int nf = 0; nf < 8; ++nf) {
            tm_g  = fmaxf(tm_g,  fmaxf(s[nf][0], s[nf][1]));
            tm_g8 = fmaxf(tm_g8, fmaxf(s[nf][2], s[nf][3]));
        }
        tm_g  = fmaxf(tm_g,  __shfl_xor_sync(0xffffffffu, tm_g, 1));
        tm_g  = fmaxf(tm_g,  __shfl_xor_sync(0xffffffffu, tm_g, 2));
        tm_g8 = fmaxf(tm_g8, __shfl_xor_sync(0xffffffffu, tm_g8, 1));
        tm_g8 = fmaxf(tm_g8, __shfl_xor_sync(0xffffffffu, tm_g8, 2));

        float mn_g = fmaxf(m_g, tm_g);
        float mn_g8 = fmaxf(m_g8, tm_g8);
        float alpha_g = expf(m_g - mn_g);
        float alpha_g8 = expf(m_g8 - mn_g8);
        m_g = mn_g; m_g8 = mn_g8;

        float sum_g = 0.f, sum_g8 = 0.f;
#pragma unroll
        for (int nf = 0; nf < 8; ++nf) {
            s[nf][0] = expf(s[nf][0] - mn_g);
            s[nf][1] = expf(s[nf][1] - mn_g);
            s[nf][2] = expf(s[nf][2] - mn_g8);
            s[nf][3] = expf(s[nf][3] - mn_g8);
            sum_g += s[nf][0] + s[nf][1];
            sum_g8 += s[nf][2] + s[nf][3];
        }
        sum_g  += __shfl_xor_sync(0xffffffffu, sum_g, 1);
        sum_g  += __shfl_xor_sync(0xffffffffu, sum_g, 2);
        sum_g8 += __shfl_xor_sync(0xffffffffu, sum_g8, 1);
        sum_g8 += __shfl_xor_sync(0xffffffffu, sum_g8, 2);
        l_g = l_g * alpha_g + sum_g;
        l_g8 = l_g8 * alpha_g8 + sum_g8;

#pragma unroll
        for (int nf = 0; nf < 8; ++nf) {
            o[nf][0] *= alpha_g;
            o[nf][1] *= alpha_g;
            o[nf][2] *= alpha_g8;
            o[nf][3] *= alpha_g8;
        }

        // ---- O += P V (bf16x3) ----
#pragma unroll
        for (int kc = 0; kc < 4; ++kc) {
            // P fragments from score frags 2kc, 2kc+1
            uint32_t ph[4], pl[4];
            {
                const float* s0 = s[2 * kc];
                const float* s1 = s[2 * kc + 1];
                float h0 = __bfloat162float(__float2bfloat16(s0[0]));
                float h1 = __bfloat162float(__float2bfloat16(s0[1]));
                float h2 = __bfloat162float(__float2bfloat16(s0[2]));
                float h3 = __bfloat162float(__float2bfloat16(s0[3]));
                float h4 = __bfloat162float(__float2bfloat16(s1[0]));
                float h5 = __bfloat162float(__float2bfloat16(s1[1]));
                float h6 = __bfloat162float(__float2bfloat16(s1[2]));
                float h7 = __bfloat162float(__float2bfloat16(s1[3]));
                ph[0] = pack_bf2(h0, h1);
                ph[1] = pack_bf2(h2, h3);
                ph[2] = pack_bf2(h4, h5);
                ph[3] = pack_bf2(h6, h7);
                pl[0] = pack_bf2(s0[0] - h0, s0[1] - h1);
                pl[1] = pack_bf2(s0[2] - h2, s0[3] - h3);
                pl[2] = pack_bf2(s1[0] - h4, s1[1] - h5);
                pl[3] = pack_bf2(s1[2] - h6, s1[3] - h7);
            }
            const int kb = kc * 32 + tg * 4;
            uint32_t vh[8][2], vl[8][2];
#pragma unroll
            for (int nf = 0; nf < 8; ++nf) {
                const char* p = sV + (nf * 8 + g) * FL_PITCH + kb;
                vh[nf][0] = *(const uint32_t*)p;
                vh[nf][1] = *(const uint32_t*)(p + 16);
                const char* p2 = sVl + (nf * 8 + g) * FL_PITCH + kb;
                vl[nf][0] = *(const uint32_t*)p2;
                vl[nf][1] = *(const uint32_t*)(p2 + 16);
            }
#pragma unroll
            for (int nf = 0; nf < 8; ++nf) {
                mma16816(o[nf], ph, vh[nf]);
                mma16816(o[nf], ph, vl[nf]);
                mma16816(o[nf], pl, vh[nf]);
            }
        }

        __syncthreads();
        if (t + 2 < nT) load_stage(st, t + 2);
        CP_COMMIT();
    }

    // ---- epilogue: normalize, write bf16 hi/lo to g_ahi/g_alo ----
    const float inv_g = 1.0f / l_g;
    const float inv_g8 = 1.0f / l_g8;
#pragma unroll
    for (int nf = 0; nf < 8; ++nf) {
        const int dk = nf * 8 + tg * 2;
        const int col = h * DKK + dk;
        {
            float v0 = o[nf][0] * inv_g, v1 = o[nf][1] * inv_g;
            size_t addr = ((size_t)b * SS + qrow) * DD + col;
            __nv_bfloat162 hh = __floats2bfloat162_rn(v0, v1);
            *(uint32_t*)(g_ahi + addr) = *(uint32_t*)&hh;
            __nv_bfloat162 ll = __floats2bfloat162_rn(v0 - __bfloat162float(hh.x),
                                                      v1 - __bfloat162float(hh.y));
            *(uint32_t*)(g_alo + addr) = *(uint32_t*)&ll;
        }
        {
            float v0 = o[nf][2] * inv_g8, v1 = o[nf][3] * inv_g8;
            size_t addr = ((size_t)b * SS + qrow + 8) * DD + col;
            __nv_bfloat162 hh = __floats2bfloat162_rn(v0, v1);
            *(uint32_t*)(g_ahi + addr) = *(uint32_t*)&hh;
            __nv_bfloat162 ll = __floats2bfloat162_rn(v0 - __bfloat162float(hh.x),
                                                      v1 - __bfloat162float(hh.y));
            *(uint32_t*)(g_alo + addr) = *(uint32_t*)&ll;
        }
    }
}

// ---------------------------------------------------------------------------
extern "C" void kernel_launch(void* const* d_in, const int* in_sizes, int n_in,
                              void* d_out, int out_size)
{
    const float* x  = (const float*)d_in[0];
    const int*   tp = (const int*)d_in[1];
    const float* Wq = (const float*)d_in[2];
    const float* bq = (const float*)d_in[3];
    const float* Wk = (const float*)d_in[4];
    const float* bk = (const float*)d_in[5];
    const float* Wv = (const float*)d_in[6];
    const float* bv = (const float*)d_in[7];
    const float* Wo = (const float*)d_in[8];
    const float* bo = (const float*)d_in[9];
    float* out = (float*)d_out;

    float *Qp, *Kp;
    __nv_bfloat16 *xhi, *xlo, *ahi, *alo, *whi, *wlo, *vthi, *vtlo;
    cudaGetSymbolAddress((void**)&Qp, g_Q);
    cudaGetSymbolAddress((void**)&Kp, g_K);
    cudaGetSymbolAddress((void**)&xhi, g_xhi);
    cudaGetSymbolAddress((void**)&xlo, g_xlo);
    cudaGetSymbolAddress((void**)&ahi, g_ahi);
    cudaGetSymbolAddress((void**)&alo, g_alo);
    cudaGetSymbolAddress((void**)&whi, g_whi);
    cudaGetSymbolAddress((void**)&wlo, g_wlo);
    cudaGetSymbolAddress((void**)&vthi, g_Vthi);
    cudaGetSymbolAddress((void**)&vtlo, g_Vtlo);

    static int attr_set = 0;
    if (!attr_set) {
        cudaFuncSetAttribute(mma_gemm<0>,
                             cudaFuncAttributeMaxDynamicSharedMemorySize, GEMM_SMEM);
        cudaFuncSetAttribute(mma_gemm<1>,
                             cudaFuncAttributeMaxDynamicSharedMemorySize, GEMM_SMEM);
        cudaFuncSetAttribute(mma_gemm<2>,
                             cudaFuncAttributeMaxDynamicSharedMemorySize, GEMM_SMEM);
        cudaFuncSetAttribute(flash_mma,
                             cudaFuncAttributeMaxDynamicSharedMemorySize, FL_SMEM);
        attr_set = 1;
    }

    const int nX = MM * DD;
    dim3 gW(DD / 32, DD / 32);
    dim3 bW(32, 8);
    dim3 gGemm(DD / 128, MM / 128);

    convert_hl<<<nX / 4 / 256, 256>>>(x, xhi, xlo, nX);

    convert_w_t<<<gW, bW>>>(Wq, whi, wlo);
    mma_gemm<1><<<gGemm, 256, GEMM_SMEM>>>(xhi, xlo, whi, wlo, bq, Qp, nullptr, nullptr);
    convert_w_t<<<gW, bW>>>(Wk, whi, wlo);
    mma_gemm<1><<<gGemm, 256, GEMM_SMEM>>>(xhi, xlo, whi, wlo, bk, Kp, nullptr, nullptr);
    convert_w_t<<<gW, bW>>>(Wv, whi, wlo);
    mma_gemm<2><<<gGemm, 256, GEMM_SMEM>>>(xhi, xlo, whi, wlo, bv, nullptr, vthi, vtlo);

    int ropeThreads = BB * HH * SS * (DKK / 2);
    rope_kernel<<<(ropeThreads + 255) / 256, 256>>>(tp);

    dim3 gFlash(SS / 64, HH, BB);
    flash_mma<<<gFlash, 128, FL_SMEM>>>();

    convert_w_t<<<gW, bW>>>(Wo, whi, wlo);
    mma_gemm<0><<<gGemm, 256, GEMM_SMEM>>>(ahi, alo, whi, wlo, bo, out, nullptr, nullptr);
}